// round 2
// baseline (speedup 1.0000x reference)
#include <cuda_runtime.h>
#include <cstdint>

// RoPE for Wan S2V: x (1, S, N, D) fp32 with S = f*h*w, N=16, D=128 (C = D/2 = 64).
// Channel c's angle source:
//   c <  22        -> freqs[f_idx][c]
//   22 <= c < 43   -> freqs[h_idx][c]
//   43 <= c < 64   -> freqs[w_idx][c]
// out pairs: (xr*cos - xi*sin, xr*sin + xi*cos), interleaved in last dim.
//
// One block per position s. Threads 0..63 stage that position's 64 cos/sin
// values into shared memory; all 512 threads each process one float4
// (= 2 complex pairs). The global x load is issued BEFORE the barrier so its
// DRAM latency overlaps the table staging.

#define F_DIM 22
#define H_DIM 21
#define C_DIM 64     // F_DIM + H_DIM + W_DIM
#define N_HEADS 16
#define D_DIM 128
#define VEC_PER_POS (N_HEADS * D_DIM / 4)   // 512 float4 per position

__global__ __launch_bounds__(VEC_PER_POS, 4)
void rope3d_kernel(const float4* __restrict__ x,
                   const float*  __restrict__ fcos,
                   const float*  __restrict__ fsin,
                   const int*    __restrict__ p_h,
                   const int*    __restrict__ p_w,
                   float4*       __restrict__ out)
{
    __shared__ float sc[C_DIM];
    __shared__ float ss[C_DIM];

    const int s = blockIdx.x;
    const int t = threadIdx.x;

    // Issue the big global load first — overlaps with table staging + barrier.
    const size_t idx = (size_t)s * VEC_PER_POS + t;
    const float4 v = x[idx];

    if (t < C_DIM) {
        // Decompose s -> (f_idx, h_idx, w_idx). Only 64 threads pay the divides.
        const int hh = *p_h;
        const int ww = *p_w;
        const int hw = hh * ww;
        const int fi  = s / hw;
        const int rem = s - fi * hw;
        const int hi  = rem / ww;
        const int wi  = rem - hi * ww;

        const int row = (t < F_DIM) ? fi : ((t < F_DIM + H_DIM) ? hi : wi);
        const int off = row * C_DIM + t;
        sc[t] = fcos[off];
        ss[t] = fsin[off];
    }
    __syncthreads();

    // float4 j (j in 0..31) within a head covers complex pairs 2j, 2j+1.
    const int j  = t & 31;
    const int c0 = 2 * j;

    const float c_a = sc[c0];
    const float s_a = ss[c0];
    const float c_b = sc[c0 + 1];
    const float s_b = ss[c0 + 1];

    float4 r;
    r.x = v.x * c_a - v.y * s_a;
    r.y = v.x * s_a + v.y * c_a;
    r.z = v.z * c_b - v.w * s_b;
    r.w = v.z * s_b + v.w * c_b;

    out[idx] = r;
}

extern "C" void kernel_launch(void* const* d_in, const int* in_sizes, int n_in,
                              void* d_out, int out_size)
{
    const float4* x    = (const float4*)d_in[0];
    const float*  fcos = (const float*)d_in[1];
    const float*  fsin = (const float*)d_in[2];
    const int*    ph   = (const int*)d_in[4];
    const int*    pw   = (const int*)d_in[5];
    float4*       out  = (float4*)d_out;

    int s_total = in_sizes[0] / (N_HEADS * D_DIM);   // 32760
    if (s_total <= 0) s_total = out_size / (N_HEADS * D_DIM);

    rope3d_kernel<<<s_total, VEC_PER_POS>>>(x, fcos, fsin, ph, pw, out);
}

// round 5
// speedup vs baseline: 1.0569x; 1.0569x over previous
#include <cuda_runtime.h>
#include <cstdint>

// RoPE for Wan S2V: x (1, S, N, D) fp32 with S = f*h*w, N=16, D=128 (C = 64).
// Channel c's angle source:
//   c <  22        -> freqs[f_idx][c]
//   22 <= c < 43   -> freqs[h_idx][c]
//   43 <= c < 64   -> freqs[w_idx][c]
// out pairs: (xr*cos - xi*sin, xr*sin + xi*cos), interleaved in last dim.
//
// R5 (= R3/R4 re-submitted after broker timeouts): 4 positions per block
// (grid = S/4). Each thread issues 4 independent LDG.128 before the single
// barrier (MLP=4); tables staged as interleaved (cos,sin) float2 so the
// per-position table read is one conflict-free LDS.128. Streaming hints
// (__ldcs/__stcs) — x/out have zero reuse. Bounds checks hoisted to a single
// block-level 'full' flag (S % 4 == 0 in practice, so the fast path is
// unpredicated).

#define F_DIM 22
#define H_DIM 21
#define C_DIM 64                       // F_DIM + H_DIM + W_DIM
#define N_HEADS 16
#define D_DIM 128
#define VEC_PER_POS (N_HEADS * D_DIM / 4)   // 512 float4 per position
#define PPB 4                          // positions per block

__global__ __launch_bounds__(VEC_PER_POS)
void rope3d_kernel(const float4* __restrict__ x,
                   const float*  __restrict__ fcos,
                   const float*  __restrict__ fsin,
                   const int*    __restrict__ p_h,
                   const int*    __restrict__ p_w,
                   float4*       __restrict__ out,
                   int s_total)
{
    __shared__ float2 tab[PPB * C_DIM];   // (cos, sin) interleaved per channel

    const int t    = threadIdx.x;
    const int base = blockIdx.x * PPB;
    const bool full = (base + PPB) <= s_total;   // uniform per block

    // ── Issue all 4 global loads up front: 4 outstanding DRAM requests/thread.
    const size_t idx0 = (size_t)base * VEC_PER_POS + t;
    float4 v[PPB];
    if (full) {
#pragma unroll
        for (int p = 0; p < PPB; p++)
            v[p] = __ldcs(x + idx0 + (size_t)p * VEC_PER_POS);
    } else {
#pragma unroll
        for (int p = 0; p < PPB; p++)
            if (base + p < s_total)
                v[p] = __ldcs(x + idx0 + (size_t)p * VEC_PER_POS);
    }

    // ── Stage the 4 positions' tables (256 threads; overlaps the loads above).
    if (t < PPB * C_DIM) {
        const int p = t >> 6;
        const int c = t & 63;
        const int s = base + p;
        if (s < s_total) {
            const int hh = *p_h;
            const int ww = *p_w;
            const int hw = hh * ww;
            const int fi  = s / hw;
            const int rem = s - fi * hw;
            const int hi  = rem / ww;
            const int wi  = rem - hi * ww;
            const int row = (c < F_DIM) ? fi : ((c < F_DIM + H_DIM) ? hi : wi);
            const int off = row * C_DIM + c;
            tab[t] = make_float2(fcos[off], fsin[off]);
        }
    }
    __syncthreads();

    // ── Compute + store. Channels (c0, c0+1) per float4; table read is one
    //    16B-aligned LDS.128 (lanes at 16B stride → conflict-free).
    const int c0 = (t & 31) * 2;

#pragma unroll
    for (int p = 0; p < PPB; p++) {
        if (!full && (base + p) >= s_total) break;
        const float4 tv = *reinterpret_cast<const float4*>(&tab[p * C_DIM + c0]);
        // tv = (cos_c0, sin_c0, cos_c0+1, sin_c0+1)
        float4 r;
        r.x = v[p].x * tv.x - v[p].y * tv.y;
        r.y = v[p].x * tv.y + v[p].y * tv.x;
        r.z = v[p].z * tv.z - v[p].w * tv.w;
        r.w = v[p].z * tv.w + v[p].w * tv.z;
        __stcs(out + idx0 + (size_t)p * VEC_PER_POS, r);
    }
}

extern "C" void kernel_launch(void* const* d_in, const int* in_sizes, int n_in,
                              void* d_out, int out_size)
{
    const float4* x    = (const float4*)d_in[0];
    const float*  fcos = (const float*)d_in[1];
    const float*  fsin = (const float*)d_in[2];
    const int*    ph   = (const int*)d_in[4];
    const int*    pw   = (const int*)d_in[5];
    float4*       out  = (float4*)d_out;

    int s_total = in_sizes[0] / (N_HEADS * D_DIM);   // 32760
    if (s_total <= 0) s_total = out_size / (N_HEADS * D_DIM);

    const int grid = (s_total + PPB - 1) / PPB;
    rope3d_kernel<<<grid, VEC_PER_POS>>>(x, fcos, fsin, ph, pw, out, s_total);
}